// round 1
// baseline (speedup 1.0000x reference)
#include <cuda_runtime.h>
#include <cuda_bf16.h>

// Problem: Y(8192x2048) = X(8192x2048) @ W(2048x2048),
// W = tensor-ring reconstruction of f0(8,64,8), f1(8,64,8), f2(8,64,8), f3(8,16,8).
//
// Factorized path (rank-64 per i2-parity):
//   B[r][l*64+a*8+b] = sum_k f0[a,i1,k]*f1[k,i2,b],  i1=r>>5, i2=2*(r&31)+l
//   C[a*8+b][i3*16+i4] = sum_k f2[b,i3,k]*f3[k,i4,a]
//   Z = X @ B                    (8192 x 128)
//   Y[:, l*1024 + c'] = Z[:, l*64 : l*64+64] @ C     (per l in {0,1})

__device__ float g_B[2048 * 128];   // 1 MB
__device__ float g_C[64 * 1024];    // 256 KB
__device__ float g_Z[8192 * 128];   // 4 MB

// ---------------------------------------------------------------------------
// Kernel 1: build B and C from the TR factors (tiny).
// ---------------------------------------------------------------------------
__global__ void build_BC(const float* __restrict__ f0,
                         const float* __restrict__ f1,
                         const float* __restrict__ f2,
                         const float* __restrict__ f3) {
    int idx = blockIdx.x * blockDim.x + threadIdx.x;
    const int NB = 2048 * 128;
    if (idx < NB) {
        int r  = idx >> 7;
        int j  = idx & 127;
        int l  = j >> 6;
        int ab = j & 63;
        int a  = ab >> 3;
        int b  = ab & 7;
        int i1 = r >> 5;
        int i2 = ((r & 31) << 1) | l;
        float s = 0.0f;
#pragma unroll
        for (int k = 0; k < 8; k++)
            s = fmaf(f0[a * 512 + i1 * 8 + k], f1[k * 512 + i2 * 8 + b], s);
        g_B[idx] = s;
    } else {
        int t = idx - NB;
        if (t < 64 * 1024) {
            int ab = t >> 10;
            int c  = t & 1023;
            int a  = ab >> 3;
            int b  = ab & 7;
            int i3 = c >> 4;
            int i4 = c & 15;
            float s = 0.0f;
#pragma unroll
            for (int k = 0; k < 8; k++)
                s = fmaf(f2[b * 512 + i3 * 8 + k], f3[k * 128 + i4 * 8 + a], s);
            g_C[t] = s;
        }
    }
}

// ---------------------------------------------------------------------------
// Kernel 2: Z = X @ B.   M=8192, K=2048, N=128.
// Block tile 64x128, BK=32, 256 threads, 4x8 per-thread micro-tile.
// ---------------------------------------------------------------------------
__global__ __launch_bounds__(256) void gemm1(const float* __restrict__ X) {
    __shared__ float Xs[32][64];    // [k][row]
    __shared__ float Bs[32][128];   // [k][col]

    const int tid = threadIdx.x;
    const int tr = tid >> 4;        // 0..15 -> rows tr*4..tr*4+3
    const int tc = tid & 15;        // 0..15 -> cols tc*8..tc*8+7
    const int m0 = blockIdx.x * 64;

    float acc[4][8];
#pragma unroll
    for (int i = 0; i < 4; i++)
#pragma unroll
        for (int j = 0; j < 8; j++) acc[i][j] = 0.0f;

    for (int k0 = 0; k0 < 2048; k0 += 32) {
        // Load X tile 64x32 (512 float4), transposed into Xs[k][row]
#pragma unroll
        for (int i = 0; i < 2; i++) {
            int p   = tid + i * 256;
            int row = p >> 3;
            int kq  = p & 7;
            float4 v = *(const float4*)&X[(m0 + row) * 2048 + k0 + kq * 4];
            Xs[kq * 4 + 0][row] = v.x;
            Xs[kq * 4 + 1][row] = v.y;
            Xs[kq * 4 + 2][row] = v.z;
            Xs[kq * 4 + 3][row] = v.w;
        }
        // Load B tile 32x128 (1024 float4 -> wait, 32*128/4 = 1024 floats4? 32*32=1024)
#pragma unroll
        for (int i = 0; i < 4; i++) {
            int p  = tid + i * 256;
            int kk = p >> 5;
            int c4 = p & 31;
            *(float4*)&Bs[kk][c4 * 4] = *(const float4*)&g_B[(k0 + kk) * 128 + c4 * 4];
        }
        __syncthreads();

#pragma unroll 8
        for (int kk = 0; kk < 32; kk++) {
            float a0 = Xs[kk][tr * 4 + 0];
            float a1 = Xs[kk][tr * 4 + 1];
            float a2 = Xs[kk][tr * 4 + 2];
            float a3 = Xs[kk][tr * 4 + 3];
            float4 b0 = *(const float4*)&Bs[kk][tc * 8];
            float4 b1 = *(const float4*)&Bs[kk][tc * 8 + 4];
            float bb[8] = {b0.x, b0.y, b0.z, b0.w, b1.x, b1.y, b1.z, b1.w};
            float aa[4] = {a0, a1, a2, a3};
#pragma unroll
            for (int i = 0; i < 4; i++)
#pragma unroll
                for (int j = 0; j < 8; j++)
                    acc[i][j] = fmaf(aa[i], bb[j], acc[i][j]);
        }
        __syncthreads();
    }

#pragma unroll
    for (int i = 0; i < 4; i++) {
        int row = m0 + tr * 4 + i;
        float4 w0 = make_float4(acc[i][0], acc[i][1], acc[i][2], acc[i][3]);
        float4 w1 = make_float4(acc[i][4], acc[i][5], acc[i][6], acc[i][7]);
        *(float4*)&g_Z[row * 128 + tc * 8]     = w0;
        *(float4*)&g_Z[row * 128 + tc * 8 + 4] = w1;
    }
}

// ---------------------------------------------------------------------------
// Kernel 3: Y[:, n0:n0+128] = Z[:, l*64 : l*64+64] @ C[:, c0:c0+128]
// Block tile 64x128, K=64 (fully resident in smem), 256 threads, 4x8 micro-tile.
// Grid: (8192/64, 2048/128) = (128, 16)
// ---------------------------------------------------------------------------
__global__ __launch_bounds__(256) void gemm2(float* __restrict__ Y) {
    __shared__ float Zs[64][64];    // [ab][row]
    __shared__ float Cs[64][128];   // [ab][c]

    const int tid = threadIdx.x;
    const int tr = tid >> 4;
    const int tc = tid & 15;
    const int m0 = blockIdx.x * 64;
    const int n0 = blockIdx.y * 128;
    const int l  = n0 >> 10;
    const int c0 = n0 & 1023;

    // Load Z tile 64x64 (1024 float4), transposed into Zs[ab][row]
#pragma unroll
    for (int i = 0; i < 4; i++) {
        int p   = tid + i * 256;
        int row = p >> 4;
        int q   = p & 15;
        float4 v = *(const float4*)&g_Z[(m0 + row) * 128 + l * 64 + q * 4];
        Zs[q * 4 + 0][row] = v.x;
        Zs[q * 4 + 1][row] = v.y;
        Zs[q * 4 + 2][row] = v.z;
        Zs[q * 4 + 3][row] = v.w;
    }
    // Load C tile 64x128 (2048 float4)
#pragma unroll
    for (int i = 0; i < 8; i++) {
        int p  = tid + i * 256;
        int ab = p >> 5;
        int c4 = p & 31;
        *(float4*)&Cs[ab][c4 * 4] = *(const float4*)&g_C[ab * 1024 + c0 + c4 * 4];
    }
    __syncthreads();

    float acc[4][8];
#pragma unroll
    for (int i = 0; i < 4; i++)
#pragma unroll
        for (int j = 0; j < 8; j++) acc[i][j] = 0.0f;

#pragma unroll 8
    for (int ab = 0; ab < 64; ab++) {
        float aa[4];
#pragma unroll
        for (int i = 0; i < 4; i++) aa[i] = Zs[ab][tr * 4 + i];
        float4 cv0 = *(const float4*)&Cs[ab][tc * 8];
        float4 cv1 = *(const float4*)&Cs[ab][tc * 8 + 4];
        float cc[8] = {cv0.x, cv0.y, cv0.z, cv0.w, cv1.x, cv1.y, cv1.z, cv1.w};
#pragma unroll
        for (int i = 0; i < 4; i++)
#pragma unroll
            for (int j = 0; j < 8; j++)
                acc[i][j] = fmaf(aa[i], cc[j], acc[i][j]);
    }

#pragma unroll
    for (int i = 0; i < 4; i++) {
        int row = m0 + tr * 4 + i;
        float4 w0 = make_float4(acc[i][0], acc[i][1], acc[i][2], acc[i][3]);
        float4 w1 = make_float4(acc[i][4], acc[i][5], acc[i][6], acc[i][7]);
        *(float4*)&Y[row * 2048 + n0 + tc * 8]     = w0;
        *(float4*)&Y[row * 2048 + n0 + tc * 8 + 4] = w1;
    }
}

// ---------------------------------------------------------------------------
extern "C" void kernel_launch(void* const* d_in, const int* in_sizes, int n_in,
                              void* d_out, int out_size) {
    const float* x  = (const float*)d_in[0];
    const float* f0 = (const float*)d_in[1];
    const float* f1 = (const float*)d_in[2];
    const float* f2 = (const float*)d_in[3];
    const float* f3 = (const float*)d_in[4];
    float* y = (float*)d_out;

    // 2048*128 + 64*1024 = 327680 elements, 256 threads -> 1280 blocks
    build_BC<<<1280, 256>>>(f0, f1, f2, f3);
    gemm1<<<128, 256>>>(x);
    dim3 g2(128, 16);
    gemm2<<<g2, 256>>>(y);
}

// round 3
// speedup vs baseline: 2.5357x; 2.5357x over previous
#include <cuda_runtime.h>
#include <cuda_bf16.h>
#include <cstdint>

// Y(8192x2048) = X(8192x2048) @ W(2048x2048), W = TR(f0,f1,f2,f3), rank-64 per i2-parity.
//   B[r][l*64+ab] = sum_k f0[a,i1,k] f1[k,i2,b],  i1=r>>5, i2=2(r&31)+l, ab=a*8+b
//   C[ab][i3*16+i4] = sum_k f2[b,i3,k] f3[k,i4,a]
//   Z = X @ B (8192x128);  Y[:, l*1024+c'] = Z[:, l*64:+64] @ C
// All GEMMs in split-bf16 (hi/lo) on HMMA with fp32 accumulate:
//   x*w ~= xhi*whi + xhi*wlo + xlo*whi   (error ~2^-16)

__device__ __nv_bfloat16 g_Bhi[2048 * 128];
__device__ __nv_bfloat16 g_Blo[2048 * 128];
__device__ __nv_bfloat16 g_Chi[64 * 1024];
__device__ __nv_bfloat16 g_Clo[64 * 1024];
__device__ __nv_bfloat16 g_Zhi[8192 * 128];
__device__ __nv_bfloat16 g_Zlo[8192 * 128];

static __device__ __forceinline__ uint32_t sptr(const void* p) {
    return (uint32_t)__cvta_generic_to_shared(p);
}
static __device__ __forceinline__ void ldm_a(uint32_t addr, uint32_t* r) {
    asm volatile("ldmatrix.sync.aligned.m8n8.x4.shared.b16 {%0,%1,%2,%3}, [%4];"
                 : "=r"(r[0]), "=r"(r[1]), "=r"(r[2]), "=r"(r[3]) : "r"(addr));
}
static __device__ __forceinline__ void ldm_bt(uint32_t addr, uint32_t* r) {
    asm volatile("ldmatrix.sync.aligned.m8n8.x4.trans.shared.b16 {%0,%1,%2,%3}, [%4];"
                 : "=r"(r[0]), "=r"(r[1]), "=r"(r[2]), "=r"(r[3]) : "r"(addr));
}
static __device__ __forceinline__ void mma_bf16(float* c, const uint32_t* a,
                                                uint32_t b0, uint32_t b1) {
    asm volatile("mma.sync.aligned.m16n8k16.row.col.f32.bf16.bf16.f32 "
                 "{%0,%1,%2,%3}, {%4,%5,%6,%7}, {%8,%9}, {%0,%1,%2,%3};"
                 : "+f"(c[0]), "+f"(c[1]), "+f"(c[2]), "+f"(c[3])
                 : "r"(a[0]), "r"(a[1]), "r"(a[2]), "r"(a[3]), "r"(b0), "r"(b1));
}
static __device__ __forceinline__ void split_store(__nv_bfloat16* hi, __nv_bfloat16* lo,
                                                   float v) {
    __nv_bfloat16 h = __float2bfloat16(v);
    *hi = h;
    *lo = __float2bfloat16(v - __bfloat162float(h));
}

// ---------------------------------------------------------------------------
// K1: build B, C from TR factors and split to bf16 hi/lo.
// ---------------------------------------------------------------------------
__global__ void build_BC(const float* __restrict__ f0, const float* __restrict__ f1,
                         const float* __restrict__ f2, const float* __restrict__ f3) {
    int idx = blockIdx.x * blockDim.x + threadIdx.x;
    const int NB = 2048 * 128;
    if (idx < NB) {
        int r = idx >> 7, j = idx & 127;
        int l = j >> 6, ab = j & 63, a = ab >> 3, b = ab & 7;
        int i1 = r >> 5, i2 = ((r & 31) << 1) | l;
        float s = 0.0f;
#pragma unroll
        for (int k = 0; k < 8; k++)
            s = fmaf(f0[a * 512 + i1 * 8 + k], f1[k * 512 + i2 * 8 + b], s);
        split_store(&g_Bhi[idx], &g_Blo[idx], s);
    } else {
        int t = idx - NB;
        if (t < 64 * 1024) {
            int ab = t >> 10, c = t & 1023;
            int a = ab >> 3, b = ab & 7, i3 = c >> 4, i4 = c & 15;
            float s = 0.0f;
#pragma unroll
            for (int k = 0; k < 8; k++)
                s = fmaf(f2[b * 512 + i3 * 8 + k], f3[k * 128 + i4 * 8 + a], s);
            split_store(&g_Chi[t], &g_Clo[t], s);
        }
    }
}

// ---------------------------------------------------------------------------
// K2: Z = X @ B. M=8192 (tiles of 64 rows), N=128, K=2048.
// 256 threads, 8 warps (2x4), warp tile 32x32, split-bf16 HMMA.
// smem: 64x40x2 (A hi/lo) + 32x136x2 (B hi/lo) = 27.6 KB
// ---------------------------------------------------------------------------
__global__ __launch_bounds__(256) void gemm1(const float* __restrict__ X) {
    const int LDA = 40;   // 64 x 40 bf16 (padded, ldmatrix conflict-free)
    const int LDB = 136;  // 32 x 136 bf16
    __shared__ __align__(16) __nv_bfloat16 Ah[64 * 40], Al[64 * 40];
    __shared__ __align__(16) __nv_bfloat16 Bh[32 * 136], Bl[32 * 136];

    const int tid = threadIdx.x, lane = tid & 31, wid = tid >> 5;
    const int m0 = blockIdx.x * 64;
    const int wm = (wid & 1) * 32, wn = (wid >> 1) * 32;

    const int xr0 = tid >> 3, xq = tid & 7;       // X: rows xr0, xr0+32; float4 col xq
    const int br = tid >> 4, bc = (tid & 15) * 8; // B: rows br, br+16; 8-col chunk bc

    float4 xf0, xf1;
    int4 bh0, bh1, bl0, bl1;

    float acc[2][4][4];
#pragma unroll
    for (int mt = 0; mt < 2; mt++)
#pragma unroll
        for (int nt = 0; nt < 4; nt++)
#pragma unroll
            for (int e = 0; e < 4; e++) acc[mt][nt][e] = 0.0f;

#define LDG_TILE(k0)                                                          \
    do {                                                                      \
        xf0 = *(const float4*)&X[(m0 + xr0) * 2048 + (k0) + xq * 4];          \
        xf1 = *(const float4*)&X[(m0 + xr0 + 32) * 2048 + (k0) + xq * 4];     \
        bh0 = *(const int4*)&g_Bhi[((k0) + br) * 128 + bc];                   \
        bh1 = *(const int4*)&g_Bhi[((k0) + br + 16) * 128 + bc];              \
        bl0 = *(const int4*)&g_Blo[((k0) + br) * 128 + bc];                   \
        bl1 = *(const int4*)&g_Blo[((k0) + br + 16) * 128 + bc];              \
    } while (0)

#define STS_TILE()                                                            \
    do {                                                                      \
        float vx[8] = {xf0.x, xf0.y, xf0.z, xf0.w, xf1.x, xf1.y, xf1.z, xf1.w}; \
        _Pragma("unroll") for (int i = 0; i < 2; i++) {                       \
            int row = xr0 + i * 32;                                           \
            _Pragma("unroll") for (int e = 0; e < 4; e++)                     \
                split_store(&Ah[row * LDA + xq * 4 + e],                      \
                            &Al[row * LDA + xq * 4 + e], vx[i * 4 + e]);      \
        }                                                                     \
        *(int4*)&Bh[br * LDB + bc] = bh0;                                     \
        *(int4*)&Bh[(br + 16) * LDB + bc] = bh1;                              \
        *(int4*)&Bl[br * LDB + bc] = bl0;                                     \
        *(int4*)&Bl[(br + 16) * LDB + bc] = bl1;                              \
    } while (0)

    LDG_TILE(0);
    STS_TILE();
    __syncthreads();

    for (int it = 0; it < 64; ++it) {
        if (it + 1 < 64) LDG_TILE((it + 1) * 32);

#pragma unroll
        for (int kk = 0; kk < 32; kk += 16) {
            uint32_t ah[2][4], al[2][4];
#pragma unroll
            for (int mt = 0; mt < 2; mt++) {
                int arow = wm + mt * 16 + (lane & 15);
                int acol = kk + ((lane >> 4) << 3);
                ldm_a(sptr(&Ah[arow * LDA + acol]), ah[mt]);
                ldm_a(sptr(&Al[arow * LDA + acol]), al[mt]);
            }
            uint32_t bh[2][4], bl[2][4];
            int brow = kk + (lane & 7) + ((lane >> 3) & 1) * 8;
#pragma unroll
            for (int h = 0; h < 2; h++) {
                int bcol = wn + h * 16 + (lane >> 4) * 8;
                ldm_bt(sptr(&Bh[brow * LDB + bcol]), bh[h]);
                ldm_bt(sptr(&Bl[brow * LDB + bcol]), bl[h]);
            }
#pragma unroll
            for (int mt = 0; mt < 2; mt++)
#pragma unroll
                for (int nt = 0; nt < 4; nt++) {
                    int h = nt >> 1, q = (nt & 1) * 2;
                    mma_bf16(acc[mt][nt], ah[mt], bh[h][q], bh[h][q + 1]);
                    mma_bf16(acc[mt][nt], ah[mt], bl[h][q], bl[h][q + 1]);
                    mma_bf16(acc[mt][nt], al[mt], bh[h][q], bh[h][q + 1]);
                }
        }
        __syncthreads();
        if (it + 1 < 64) {
            STS_TILE();
            __syncthreads();
        }
    }
#undef LDG_TILE
#undef STS_TILE

    // Epilogue: split Z to bf16 hi/lo pairs (cols 2j,2j+1 contiguous).
#pragma unroll
    for (int mt = 0; mt < 2; mt++)
#pragma unroll
        for (int nt = 0; nt < 4; nt++) {
            int row = m0 + wm + mt * 16 + (lane >> 2);
            int col = wn + nt * 8 + (lane & 3) * 2;
            const float* c = acc[mt][nt];
#pragma unroll
            for (int half = 0; half < 2; half++) {
                int r = row + half * 8;
                float v0 = c[half * 2 + 0], v1 = c[half * 2 + 1];
                __nv_bfloat16 h0 = __float2bfloat16(v0), h1 = __float2bfloat16(v1);
                __nv_bfloat162 hi2(h0, h1);
                __nv_bfloat162 lo2(__float2bfloat16(v0 - __bfloat162float(h0)),
                                   __float2bfloat16(v1 - __bfloat162float(h1)));
                *(__nv_bfloat162*)&g_Zhi[r * 128 + col] = hi2;
                *(__nv_bfloat162*)&g_Zlo[r * 128 + col] = lo2;
            }
        }
}

// ---------------------------------------------------------------------------
// K3: Y[:, n0:n0+64] = Z[:, l*64:+64] @ C[:, c0:c0+64]. K=64 resident.
// Grid (128, 32). 256 threads, 8 warps (2x4), warp tile 32x16, split-bf16 HMMA.
// smem: 4 buffers of 64x72x2B = 36 KB < 48 KB.
// ---------------------------------------------------------------------------
__global__ __launch_bounds__(256) void gemm2(float* __restrict__ Y) {
    const int LDA = 72;   // 64 x 72
    const int LDB = 72;   // 64 x 72
    __shared__ __align__(16) __nv_bfloat16 Zh[64 * 72], Zl[64 * 72];
    __shared__ __align__(16) __nv_bfloat16 Ch[64 * 72], Cl[64 * 72];

    const int tid = threadIdx.x, lane = tid & 31, wid = tid >> 5;
    const int m0 = blockIdx.x * 64;
    const int n0 = blockIdx.y * 64;
    const int l = n0 >> 10;
    const int c0 = n0 & 1023;
    const int wm = (wid & 1) * 32, wn = (wid >> 1) * 16;

    // Load Z slab 64x64 (hi/lo) and C chunk 64x64 (hi/lo)
#pragma unroll
    for (int i = 0; i < 2; i++) {
        int p = tid + i * 256;
        int row = p >> 3, kq = (p & 7) * 8;
        *(int4*)&Zh[row * LDA + kq] = *(const int4*)&g_Zhi[(m0 + row) * 128 + l * 64 + kq];
        *(int4*)&Zl[row * LDA + kq] = *(const int4*)&g_Zlo[(m0 + row) * 128 + l * 64 + kq];
        *(int4*)&Ch[row * LDB + kq] = *(const int4*)&g_Chi[row * 1024 + c0 + kq];
        *(int4*)&Cl[row * LDB + kq] = *(const int4*)&g_Clo[row * 1024 + c0 + kq];
    }
    __syncthreads();

    float acc[2][2][4];
#pragma unroll
    for (int mt = 0; mt < 2; mt++)
#pragma unroll
        for (int nt = 0; nt < 2; nt++)
#pragma unroll
            for (int e = 0; e < 4; e++) acc[mt][nt][e] = 0.0f;

#pragma unroll
    for (int kk = 0; kk < 64; kk += 16) {
        uint32_t ah[2][4], al[2][4];
#pragma unroll
        for (int mt = 0; mt < 2; mt++) {
            int arow = wm + mt * 16 + (lane & 15);
            int acol = kk + ((lane >> 4) << 3);
            ldm_a(sptr(&Zh[arow * LDA + acol]), ah[mt]);
            ldm_a(sptr(&Zl[arow * LDA + acol]), al[mt]);
        }
        uint32_t bh[4], bl[4];
        int brow = kk + (lane & 7) + ((lane >> 3) & 1) * 8;
        int bcol = wn + (lane >> 4) * 8;
        ldm_bt(sptr(&Ch[brow * LDB + bcol]), bh);
        ldm_bt(sptr(&Cl[brow * LDB + bcol]), bl);
#pragma unroll
        for (int mt = 0; mt < 2; mt++)
#pragma unroll
            for (int nt = 0; nt < 2; nt++) {
                int q = nt * 2;
                mma_bf16(acc[mt][nt], ah[mt], bh[q], bh[q + 1]);
                mma_bf16(acc[mt][nt], ah[mt], bl[q], bl[q + 1]);
                mma_bf16(acc[mt][nt], al[mt], bh[q], bh[q + 1]);
            }
    }

#pragma unroll
    for (int mt = 0; mt < 2; mt++)
#pragma unroll
        for (int nt = 0; nt < 2; nt++) {
            int row = m0 + wm + mt * 16 + (lane >> 2);
            int col = n0 + wn + nt * 8 + (lane & 3) * 2;
            const float* c = acc[mt][nt];
            *(float2*)&Y[row * 2048 + col] = make_float2(c[0], c[1]);
            *(float2*)&Y[(row + 8) * 2048 + col] = make_float2(c[2], c[3]);
        }
}

// ---------------------------------------------------------------------------
extern "C" void kernel_launch(void* const* d_in, const int* in_sizes, int n_in,
                              void* d_out, int out_size) {
    const float* x = (const float*)d_in[0];
    const float* f0 = (const float*)d_in[1];
    const float* f1 = (const float*)d_in[2];
    const float* f2 = (const float*)d_in[3];
    const float* f3 = (const float*)d_in[4];
    float* y = (float*)d_out;

    build_BC<<<1280, 256>>>(f0, f1, f2, f3);
    gemm1<<<128, 256>>>(x);
    dim3 g2(128, 32);
    gemm2<<<g2, 256>>>(y);
}

// round 6
// speedup vs baseline: 3.0822x; 1.2155x over previous
#include <cuda_runtime.h>
#include <cuda_bf16.h>
#include <cstdint>

// Y(8192x2048) = X(8192x2048) @ W(2048x2048), W = TR(f0,f1,f2,f3), rank-64 per i2-parity.
//   B[r][l*64+ab] = sum_k f0[a,i1,k] f1[k,i2,b],  i1=r>>5, i2=2(r&31)+l, ab=a*8+b
//   C[ab][i3*16+i4] = sum_k f2[b,i3,k] f3[k,i4,a]
//   Z = X @ B (8192x128);  Y[:, l*1024+c'] = Z[:, l*64:+64] @ C
// Split-bf16 (hi/lo) HMMA with fp32 accumulate: x*w ~= xh*wh + xh*wl + xl*wh.

__device__ __nv_bfloat16 g_Bhi[2048 * 128];
__device__ __nv_bfloat16 g_Blo[2048 * 128];
__device__ __nv_bfloat16 g_Chi[64 * 1024];
__device__ __nv_bfloat16 g_Clo[64 * 1024];
__device__ __nv_bfloat16 g_Zhi[8192 * 128];
__device__ __nv_bfloat16 g_Zlo[8192 * 128];

static __device__ __forceinline__ uint32_t sptr(const void* p) {
    return (uint32_t)__cvta_generic_to_shared(p);
}
static __device__ __forceinline__ void ldm_a(uint32_t addr, uint32_t* r) {
    asm volatile("ldmatrix.sync.aligned.m8n8.x4.shared.b16 {%0,%1,%2,%3}, [%4];"
                 : "=r"(r[0]), "=r"(r[1]), "=r"(r[2]), "=r"(r[3]) : "r"(addr));
}
static __device__ __forceinline__ void ldm_bt(uint32_t addr, uint32_t* r) {
    asm volatile("ldmatrix.sync.aligned.m8n8.x4.trans.shared.b16 {%0,%1,%2,%3}, [%4];"
                 : "=r"(r[0]), "=r"(r[1]), "=r"(r[2]), "=r"(r[3]) : "r"(addr));
}
static __device__ __forceinline__ void mma_bf16(float* c, const uint32_t* a,
                                                uint32_t b0, uint32_t b1) {
    asm volatile("mma.sync.aligned.m16n8k16.row.col.f32.bf16.bf16.f32 "
                 "{%0,%1,%2,%3}, {%4,%5,%6,%7}, {%8,%9}, {%0,%1,%2,%3};"
                 : "+f"(c[0]), "+f"(c[1]), "+f"(c[2]), "+f"(c[3])
                 : "r"(a[0]), "r"(a[1]), "r"(a[2]), "r"(a[3]), "r"(b0), "r"(b1));
}
#define CP16(dst, src)                                                        \
    asm volatile("cp.async.cg.shared.global [%0], [%1], 16;" ::"r"(dst), "l"(src))
#define CP_COMMIT() asm volatile("cp.async.commit_group;")
#define CP_WAIT0() asm volatile("cp.async.wait_group 0;")

static __device__ __forceinline__ uint32_t pack2(__nv_bfloat16 a, __nv_bfloat16 b) {
    __nv_bfloat162 t(a, b);
    return *reinterpret_cast<uint32_t*>(&t);
}
static __device__ __forceinline__ void split4(float4 v, uint2& hi, uint2& lo) {
    float f[4] = {v.x, v.y, v.z, v.w};
    __nv_bfloat16 h[4], l[4];
#pragma unroll
    for (int e = 0; e < 4; e++) {
        h[e] = __float2bfloat16(f[e]);
        l[e] = __float2bfloat16(f[e] - __bfloat162float(h[e]));
    }
    hi = make_uint2(pack2(h[0], h[1]), pack2(h[2], h[3]));
    lo = make_uint2(pack2(l[0], l[1]), pack2(l[2], l[3]));
}
static __device__ __forceinline__ void split_store(__nv_bfloat16* hi, __nv_bfloat16* lo,
                                                   float v) {
    __nv_bfloat16 h = __float2bfloat16(v);
    *hi = h;
    *lo = __float2bfloat16(v - __bfloat162float(h));
}

// ---------------------------------------------------------------------------
// K1: build B, C and split to bf16 hi/lo.
// ---------------------------------------------------------------------------
__global__ void build_BC(const float* __restrict__ f0, const float* __restrict__ f1,
                         const float* __restrict__ f2, const float* __restrict__ f3) {
    int idx = blockIdx.x * blockDim.x + threadIdx.x;
    const int NB = 2048 * 128;
    if (idx < NB) {
        int r = idx >> 7, j = idx & 127;
        int l = j >> 6, ab = j & 63, a = ab >> 3, b = ab & 7;
        int i1 = r >> 5, i2 = ((r & 31) << 1) | l;
        float s = 0.0f;
#pragma unroll
        for (int k = 0; k < 8; k++)
            s = fmaf(f0[a * 512 + i1 * 8 + k], f1[k * 512 + i2 * 8 + b], s);
        split_store(&g_Bhi[idx], &g_Blo[idx], s);
    } else {
        int t = idx - NB;
        if (t < 64 * 1024) {
            int ab = t >> 10, c = t & 1023;
            int a = ab >> 3, b = ab & 7, i3 = c >> 4, i4 = c & 15;
            float s = 0.0f;
#pragma unroll
            for (int k = 0; k < 8; k++)
                s = fmaf(f2[b * 512 + i3 * 8 + k], f3[k * 128 + i4 * 8 + a], s);
            split_store(&g_Chi[t], &g_Clo[t], s);
        }
    }
}

// ---------------------------------------------------------------------------
// K2: Z = X @ B. M=8192 (64-row tiles), N=128, K=2048.
// 256 threads, 8 warps (2Mx4N), warp tile 32x32, split-bf16 HMMA.
// Double-buffered dynamic smem (2 x 27648 B), cp.async for B, LDG+pack for X.
// ---------------------------------------------------------------------------
__global__ __launch_bounds__(256) void gemm1(const float* __restrict__ X) {
    const int LDA = 40;   // 64 x 40 bf16 per stage
    const int LDB = 136;  // 32 x 136 bf16 per stage
    const int STAGE = 13824;  // elems per stage
    const int A_H = 0, A_L = 2560, B_H = 5120, B_L = 9472;
    extern __shared__ __align__(16) __nv_bfloat16 sm1[];

    const int tid = threadIdx.x, lane = tid & 31, wid = tid >> 5;
    const int m0 = blockIdx.x * 64;
    const int wm = (wid & 1) * 32, wn = (wid >> 1) * 32;

    const int xr0 = tid >> 3, xq = tid & 7;        // X: rows xr0, xr0+32; col chunk xq*4
    const int br = tid >> 4, bc = (tid & 15) * 8;  // B: rows br, br+16; col chunk bc

    float4 xf0, xf1;

    float acc[2][4][4];
#pragma unroll
    for (int mt = 0; mt < 2; mt++)
#pragma unroll
        for (int nt = 0; nt < 4; nt++)
#pragma unroll
            for (int e = 0; e < 4; e++) acc[mt][nt][e] = 0.0f;

    // ---- prologue: stage 0 ----
    {
        __nv_bfloat16* s = sm1;
        uint32_t d;
        d = sptr(&s[B_H + br * LDB + bc]);        CP16(d, &g_Bhi[br * 128 + bc]);
        d = sptr(&s[B_H + (br + 16) * LDB + bc]); CP16(d, &g_Bhi[(br + 16) * 128 + bc]);
        d = sptr(&s[B_L + br * LDB + bc]);        CP16(d, &g_Blo[br * 128 + bc]);
        d = sptr(&s[B_L + (br + 16) * LDB + bc]); CP16(d, &g_Blo[(br + 16) * 128 + bc]);
        CP_COMMIT();
        xf0 = *(const float4*)&X[(m0 + xr0) * 2048 + xq * 4];
        xf1 = *(const float4*)&X[(m0 + xr0 + 32) * 2048 + xq * 4];
        uint2 h0, l0, h1, l1;
        split4(xf0, h0, l0);
        split4(xf1, h1, l1);
        *(uint2*)&s[A_H + xr0 * LDA + xq * 4] = h0;
        *(uint2*)&s[A_L + xr0 * LDA + xq * 4] = l0;
        *(uint2*)&s[A_H + (xr0 + 32) * LDA + xq * 4] = h1;
        *(uint2*)&s[A_L + (xr0 + 32) * LDA + xq * 4] = l1;
    }

    for (int it = 0; it < 64; ++it) {
        CP_WAIT0();
        __syncthreads();
        __nv_bfloat16* cur = sm1 + (it & 1) * STAGE;
        __nv_bfloat16* nxt = sm1 + ((it + 1) & 1) * STAGE;

        const bool more = (it + 1 < 64);
        if (more) {
            int k0 = (it + 1) * 32;
            uint32_t d;
            d = sptr(&nxt[B_H + br * LDB + bc]);
            CP16(d, &g_Bhi[(k0 + br) * 128 + bc]);
            d = sptr(&nxt[B_H + (br + 16) * LDB + bc]);
            CP16(d, &g_Bhi[(k0 + br + 16) * 128 + bc]);
            d = sptr(&nxt[B_L + br * LDB + bc]);
            CP16(d, &g_Blo[(k0 + br) * 128 + bc]);
            d = sptr(&nxt[B_L + (br + 16) * LDB + bc]);
            CP16(d, &g_Blo[(k0 + br + 16) * 128 + bc]);
            CP_COMMIT();
            xf0 = *(const float4*)&X[(m0 + xr0) * 2048 + k0 + xq * 4];
            xf1 = *(const float4*)&X[(m0 + xr0 + 32) * 2048 + k0 + xq * 4];
        }

        // ---- compute current stage ----
#pragma unroll
        for (int kk = 0; kk < 32; kk += 16) {
            uint32_t ah[2][4], al[2][4];
#pragma unroll
            for (int mt = 0; mt < 2; mt++) {
                int arow = wm + mt * 16 + (lane & 15);
                int acol = kk + ((lane >> 4) << 3);
                ldm_a(sptr(&cur[A_H + arow * LDA + acol]), ah[mt]);
                ldm_a(sptr(&cur[A_L + arow * LDA + acol]), al[mt]);
            }
            uint32_t bh[2][4], bl[2][4];
            int brow = kk + (lane & 7) + ((lane >> 3) & 1) * 8;
#pragma unroll
            for (int h = 0; h < 2; h++) {
                int bcol = wn + h * 16 + (lane >> 4) * 8;
                ldm_bt(sptr(&cur[B_H + brow * LDB + bcol]), bh[h]);
                ldm_bt(sptr(&cur[B_L + brow * LDB + bcol]), bl[h]);
            }
#pragma unroll
            for (int mt = 0; mt < 2; mt++)
#pragma unroll
                for (int nt = 0; nt < 4; nt++) {
                    int h = nt >> 1, q = (nt & 1) * 2;
                    mma_bf16(acc[mt][nt], ah[mt], bh[h][q], bh[h][q + 1]);
                    mma_bf16(acc[mt][nt], ah[mt], bl[h][q], bl[h][q + 1]);
                    mma_bf16(acc[mt][nt], al[mt], bh[h][q], bh[h][q + 1]);
                }
        }

        if (more) {
            uint2 h0, l0, h1, l1;
            split4(xf0, h0, l0);
            split4(xf1, h1, l1);
            *(uint2*)&nxt[A_H + xr0 * LDA + xq * 4] = h0;
            *(uint2*)&nxt[A_L + xr0 * LDA + xq * 4] = l0;
            *(uint2*)&nxt[A_H + (xr0 + 32) * LDA + xq * 4] = h1;
            *(uint2*)&nxt[A_L + (xr0 + 32) * LDA + xq * 4] = l1;
        }
    }

    // Epilogue: split Z to bf16 hi/lo (cols 2j,2j+1 contiguous).
#pragma unroll
    for (int mt = 0; mt < 2; mt++)
#pragma unroll
        for (int nt = 0; nt < 4; nt++) {
            int row = m0 + wm + mt * 16 + (lane >> 2);
            int col = wn + nt * 8 + (lane & 3) * 2;
            const float* c = acc[mt][nt];
#pragma unroll
            for (int half = 0; half < 2; half++) {
                int r = row + half * 8;
                float v0 = c[half * 2 + 0], v1 = c[half * 2 + 1];
                __nv_bfloat16 h0 = __float2bfloat16(v0), h1 = __float2bfloat16(v1);
                __nv_bfloat162 hi2(h0, h1);
                __nv_bfloat162 lo2(__float2bfloat16(v0 - __bfloat162float(h0)),
                                   __float2bfloat16(v1 - __bfloat162float(h1)));
                *(__nv_bfloat162*)&g_Zhi[r * 128 + col] = hi2;
                *(__nv_bfloat162*)&g_Zlo[r * 128 + col] = lo2;
            }
        }
}

// ---------------------------------------------------------------------------
// K3: Y[:, n0:n0+128] = Z[:, l*64:+64] @ C[:, c0:c0+128]. K=64 resident.
// Grid (128, 16). 256 threads, warp tile 32x32, split-bf16 HMMA.
// Dynamic smem 53248 B, cp.async loads.
// ---------------------------------------------------------------------------
__global__ __launch_bounds__(256) void gemm2(float* __restrict__ Y) {
    const int LDA = 72;   // Z: 64 x 72
    const int LDB = 136;  // C: 64 x 136
    const int Z_H = 0, Z_L = 4608, C_H = 9216, C_L = 17920;
    extern __shared__ __align__(16) __nv_bfloat16 sm2[];

    const int tid = threadIdx.x, lane = tid & 31, wid = tid >> 5;
    const int m0 = blockIdx.x * 64;
    const int n0 = blockIdx.y * 128;
    const int l = n0 >> 10;
    const int c0 = n0 & 1023;
    const int wm = (wid & 1) * 32, wn = (wid >> 1) * 32;

    // Z slab 64x64 hi/lo via cp.async
#pragma unroll
    for (int i = 0; i < 2; i++) {
        int p = tid + i * 256;
        int row = p >> 3, kq = (p & 7) * 8;
        CP16(sptr(&sm2[Z_H + row * LDA + kq]), &g_Zhi[(m0 + row) * 128 + l * 64 + kq]);
        CP16(sptr(&sm2[Z_L + row * LDA + kq]), &g_Zlo[(m0 + row) * 128 + l * 64 + kq]);
    }
    // C chunk 64x128 hi/lo via cp.async
#pragma unroll
    for (int i = 0; i < 4; i++) {
        int p = tid + i * 256;
        int row = p >> 4, cc = (p & 15) * 8;
        CP16(sptr(&sm2[C_H + row * LDB + cc]), &g_Chi[row * 1024 + c0 + cc]);
        CP16(sptr(&sm2[C_L + row * LDB + cc]), &g_Clo[row * 1024 + c0 + cc]);
    }
    CP_COMMIT();
    CP_WAIT0();
    __syncthreads();

    float acc[2][4][4];
#pragma unroll
    for (int mt = 0; mt < 2; mt++)
#pragma unroll
        for (int nt = 0; nt < 4; nt++)
#pragma unroll
            for (int e = 0; e < 4; e++) acc[mt][nt][e] = 0.0f;

#pragma unroll
    for (int kk = 0; kk < 64; kk += 16) {
        uint32_t ah[2][4], al[2][4];
#pragma unroll
        for (int mt = 0; mt < 2; mt++) {
            int arow = wm + mt * 16 + (lane & 15);
            int acol = kk + ((lane >> 4) << 3);
            ldm_a(sptr(&sm2[Z_H + arow * LDA + acol]), ah[mt]);
            ldm_a(sptr(&sm2[Z_L + arow * LDA + acol]), al[mt]);
        }
        uint32_t bh[2][4], bl[2][4];
        int brow = kk + (lane & 7) + ((lane >> 3) & 1) * 8;
#pragma unroll
        for (int h = 0; h < 2; h++) {
            int bcol = wn + h * 16 + (lane >> 4) * 8;
            ldm_bt(sptr(&sm2[C_H + brow * LDB + bcol]), bh[h]);
            ldm_bt(sptr(&sm2[C_L + brow * LDB + bcol]), bl[h]);
        }
#pragma unroll
        for (int mt = 0; mt < 2; mt++)
#pragma unroll
            for (int nt = 0; nt < 4; nt++) {
                int h = nt >> 1, q = (nt & 1) * 2;
                mma_bf16(acc[mt][nt], ah[mt], bh[h][q], bh[h][q + 1]);
                mma_bf16(acc[mt][nt], ah[mt], bl[h][q], bl[h][q + 1]);
                mma_bf16(acc[mt][nt], al[mt], bh[h][q], bh[h][q + 1]);
            }
    }

#pragma unroll
    for (int mt = 0; mt < 2; mt++)
#pragma unroll
        for (int nt = 0; nt < 4; nt++) {
            int row = m0 + wm + mt * 16 + (lane >> 2);
            int col = n0 + wn + nt * 8 + (lane & 3) * 2;
            const float* c = acc[mt][nt];
            *(float2*)&Y[row * 2048 + col] = make_float2(c[0], c[1]);
            *(float2*)&Y[(row + 8) * 2048 + col] = make_float2(c[2], c[3]);
        }
}

// ---------------------------------------------------------------------------
extern "C" void kernel_launch(void* const* d_in, const int* in_sizes, int n_in,
                              void* d_out, int out_size) {
    // Non-stream, deterministic, capture-safe attribute setup.
    cudaFuncSetAttribute(gemm1, cudaFuncAttributeMaxDynamicSharedMemorySize, 55296);
    cudaFuncSetAttribute(gemm2, cudaFuncAttributeMaxDynamicSharedMemorySize, 53248);

    const float* x = (const float*)d_in[0];
    const float* f0 = (const float*)d_in[1];
    const float* f1 = (const float*)d_in[2];
    const float* f2 = (const float*)d_in[3];
    const float* f3 = (const float*)d_in[4];
    float* y = (float*)d_out;

    build_BC<<<1280, 256>>>(f0, f1, f2, f3);
    gemm1<<<128, 256, 55296>>>(x);
    dim3 g2(128, 16);
    gemm2<<<g2, 256, 53248>>>(y);
}

// round 10
// speedup vs baseline: 3.2728x; 1.0618x over previous
#include <cuda_runtime.h>
#include <cuda_bf16.h>
#include <cuda_fp16.h>
#include <cstdint>

// Y(8192x2048) = X(8192x2048) @ W(2048x2048), W = TR(f0,f1,f2,f3), rank-64 per i2-parity.
//   B[r][l*64+ab] = sum_k f0[a,i1,k] f1[k,i2,b],  i1=r>>5, i2=2(r&31)+l, ab=a*8+b
//   C[ab][i3*16+i4] = sum_k f2[b,i3,k] f3[k,i4,a]
//   Z = X @ B (8192x128);  Y[:, l*1024+c'] = Z[:, l*64:+64] @ C
// gemm1: SINGLE-PASS fp16 HMMA (X,B -> fp16, fp32 accumulate; err ~2^-12).
// gemm2: 3-pass split-bf16 HMMA (err ~2^-16, negligible).

__device__ __half        g_Bf16[2048 * 128];
__device__ __nv_bfloat16 g_Chi[64 * 1024];
__device__ __nv_bfloat16 g_Clo[64 * 1024];
__device__ __nv_bfloat16 g_Zhi[8192 * 128];
__device__ __nv_bfloat16 g_Zlo[8192 * 128];

static __device__ __forceinline__ uint32_t sptr(const void* p) {
    return (uint32_t)__cvta_generic_to_shared(p);
}
static __device__ __forceinline__ void ldm_a(uint32_t addr, uint32_t* r) {
    asm volatile("ldmatrix.sync.aligned.m8n8.x4.shared.b16 {%0,%1,%2,%3}, [%4];"
                 : "=r"(r[0]), "=r"(r[1]), "=r"(r[2]), "=r"(r[3]) : "r"(addr));
}
static __device__ __forceinline__ void ldm_bt(uint32_t addr, uint32_t* r) {
    asm volatile("ldmatrix.sync.aligned.m8n8.x4.trans.shared.b16 {%0,%1,%2,%3}, [%4];"
                 : "=r"(r[0]), "=r"(r[1]), "=r"(r[2]), "=r"(r[3]) : "r"(addr));
}
static __device__ __forceinline__ void mma_bf16(float* c, const uint32_t* a,
                                                uint32_t b0, uint32_t b1) {
    asm volatile("mma.sync.aligned.m16n8k16.row.col.f32.bf16.bf16.f32 "
                 "{%0,%1,%2,%3}, {%4,%5,%6,%7}, {%8,%9}, {%0,%1,%2,%3};"
                 : "+f"(c[0]), "+f"(c[1]), "+f"(c[2]), "+f"(c[3])
                 : "r"(a[0]), "r"(a[1]), "r"(a[2]), "r"(a[3]), "r"(b0), "r"(b1));
}
static __device__ __forceinline__ void mma_f16(float* c, const uint32_t* a,
                                               uint32_t b0, uint32_t b1) {
    asm volatile("mma.sync.aligned.m16n8k16.row.col.f32.f16.f16.f32 "
                 "{%0,%1,%2,%3}, {%4,%5,%6,%7}, {%8,%9}, {%0,%1,%2,%3};"
                 : "+f"(c[0]), "+f"(c[1]), "+f"(c[2]), "+f"(c[3])
                 : "r"(a[0]), "r"(a[1]), "r"(a[2]), "r"(a[3]), "r"(b0), "r"(b1));
}
#define CP16(dst, src)                                                        \
    asm volatile("cp.async.cg.shared.global [%0], [%1], 16;" ::"r"(dst), "l"(src))
#define CP_COMMIT() asm volatile("cp.async.commit_group;")
#define CP_WAIT0() asm volatile("cp.async.wait_group 0;")

static __device__ __forceinline__ uint2 f4_to_h4(float4 v) {
    __half2 p0 = __floats2half2_rn(v.x, v.y);
    __half2 p1 = __floats2half2_rn(v.z, v.w);
    return make_uint2(*reinterpret_cast<uint32_t*>(&p0),
                      *reinterpret_cast<uint32_t*>(&p1));
}
static __device__ __forceinline__ void split_store(__nv_bfloat16* hi, __nv_bfloat16* lo,
                                                   float v) {
    __nv_bfloat16 h = __float2bfloat16(v);
    *hi = h;
    *lo = __float2bfloat16(v - __bfloat162float(h));
}

// ---------------------------------------------------------------------------
// K1: build B (fp16) and C (bf16 hi/lo) from TR factors.
// ---------------------------------------------------------------------------
__global__ void build_BC(const float* __restrict__ f0, const float* __restrict__ f1,
                         const float* __restrict__ f2, const float* __restrict__ f3) {
    int idx = blockIdx.x * blockDim.x + threadIdx.x;
    const int NB = 2048 * 128;
    if (idx < NB) {
        int r = idx >> 7, j = idx & 127;
        int l = j >> 6, ab = j & 63, a = ab >> 3, b = ab & 7;
        int i1 = r >> 5, i2 = ((r & 31) << 1) | l;
        float s = 0.0f;
#pragma unroll
        for (int k = 0; k < 8; k++)
            s = fmaf(f0[a * 512 + i1 * 8 + k], f1[k * 512 + i2 * 8 + b], s);
        g_Bf16[idx] = __float2half_rn(s);
    } else {
        int t = idx - NB;
        if (t < 64 * 1024) {
            int ab = t >> 10, c = t & 1023;
            int a = ab >> 3, b = ab & 7, i3 = c >> 4, i4 = c & 15;
            float s = 0.0f;
#pragma unroll
            for (int k = 0; k < 8; k++)
                s = fmaf(f2[b * 512 + i3 * 8 + k], f3[k * 128 + i4 * 8 + a], s);
            split_store(&g_Chi[t], &g_Clo[t], s);
        }
    }
}

// ---------------------------------------------------------------------------
// K2: Z = X @ B. M=8192 (64-row tiles), N=128, K=2048. SINGLE-PASS fp16.
// 256 threads, 8 warps (2Mx4N), warp tile 32x32. Double-buffered static smem.
// ---------------------------------------------------------------------------
__global__ __launch_bounds__(256) void gemm1(const float* __restrict__ X) {
    const int LDA = 40;   // 64 x 40 fp16 per stage
    const int LDB = 136;  // 32 x 136 fp16 per stage
    __shared__ __align__(16) __half Ah[2][64 * 40];
    __shared__ __align__(16) __half Bh[2][32 * 136];

    const int tid = threadIdx.x, lane = tid & 31, wid = tid >> 5;
    const int m0 = blockIdx.x * 64;
    const int wm = (wid & 1) * 32, wn = (wid >> 1) * 32;

    const int xr0 = tid >> 3, xq = tid & 7;        // X rows xr0, xr0+32; float4 col xq
    const int br = tid >> 4, bc = (tid & 15) * 8;  // B rows br, br+16; col chunk bc

    float4 xf0, xf1;

    float acc[2][4][4];
#pragma unroll
    for (int mt = 0; mt < 2; mt++)
#pragma unroll
        for (int nt = 0; nt < 4; nt++)
#pragma unroll
            for (int e = 0; e < 4; e++) acc[mt][nt][e] = 0.0f;

    // ---- prologue: stage 0 ----
    {
        CP16(sptr(&Bh[0][br * LDB + bc]), &g_Bf16[br * 128 + bc]);
        CP16(sptr(&Bh[0][(br + 16) * LDB + bc]), &g_Bf16[(br + 16) * 128 + bc]);
        CP_COMMIT();
        xf0 = *(const float4*)&X[(m0 + xr0) * 2048 + xq * 4];
        xf1 = *(const float4*)&X[(m0 + xr0 + 32) * 2048 + xq * 4];
        *(uint2*)&Ah[0][xr0 * LDA + xq * 4] = f4_to_h4(xf0);
        *(uint2*)&Ah[0][(xr0 + 32) * LDA + xq * 4] = f4_to_h4(xf1);
    }

    for (int it = 0; it < 64; ++it) {
        CP_WAIT0();
        __syncthreads();
        const int cur = it & 1, nxt = (it + 1) & 1;
        const bool more = (it + 1 < 64);

        if (more) {
            int k0 = (it + 1) * 32;
            CP16(sptr(&Bh[nxt][br * LDB + bc]), &g_Bf16[(k0 + br) * 128 + bc]);
            CP16(sptr(&Bh[nxt][(br + 16) * LDB + bc]), &g_Bf16[(k0 + br + 16) * 128 + bc]);
            CP_COMMIT();
            xf0 = *(const float4*)&X[(m0 + xr0) * 2048 + k0 + xq * 4];
            xf1 = *(const float4*)&X[(m0 + xr0 + 32) * 2048 + k0 + xq * 4];
        }

        // ---- compute current stage ----
#pragma unroll
        for (int kk = 0; kk < 32; kk += 16) {
            uint32_t ah[2][4];
#pragma unroll
            for (int mt = 0; mt < 2; mt++) {
                int arow = wm + mt * 16 + (lane & 15);
                int acol = kk + ((lane >> 4) << 3);
                ldm_a(sptr(&Ah[cur][arow * LDA + acol]), ah[mt]);
            }
            uint32_t bhr[2][4];
            int brow = kk + (lane & 7) + ((lane >> 3) & 1) * 8;
#pragma unroll
            for (int h = 0; h < 2; h++) {
                int bcol = wn + h * 16 + (lane >> 4) * 8;
                ldm_bt(sptr(&Bh[cur][brow * LDB + bcol]), bhr[h]);
            }
#pragma unroll
            for (int mt = 0; mt < 2; mt++)
#pragma unroll
                for (int nt = 0; nt < 4; nt++) {
                    int h = nt >> 1, q = (nt & 1) * 2;
                    mma_f16(acc[mt][nt], ah[mt], bhr[h][q], bhr[h][q + 1]);
                }
        }

        if (more) {
            *(uint2*)&Ah[nxt][xr0 * LDA + xq * 4] = f4_to_h4(xf0);
            *(uint2*)&Ah[nxt][(xr0 + 32) * LDA + xq * 4] = f4_to_h4(xf1);
        }
    }

    // Epilogue: split fp32 Z acc to bf16 hi/lo (cols 2j,2j+1 contiguous).
#pragma unroll
    for (int mt = 0; mt < 2; mt++)
#pragma unroll
        for (int nt = 0; nt < 4; nt++) {
            int row = m0 + wm + mt * 16 + (lane >> 2);
            int col = wn + nt * 8 + (lane & 3) * 2;
            const float* c = acc[mt][nt];
#pragma unroll
            for (int half = 0; half < 2; half++) {
                int r = row + half * 8;
                float v0 = c[half * 2 + 0], v1 = c[half * 2 + 1];
                __nv_bfloat16 h0 = __float2bfloat16(v0), h1 = __float2bfloat16(v1);
                __nv_bfloat162 hi2(h0, h1);
                __nv_bfloat162 lo2(__float2bfloat16(v0 - __bfloat162float(h0)),
                                   __float2bfloat16(v1 - __bfloat162float(h1)));
                *(__nv_bfloat162*)&g_Zhi[r * 128 + col] = hi2;
                *(__nv_bfloat162*)&g_Zlo[r * 128 + col] = lo2;
            }
        }
}

// ---------------------------------------------------------------------------
// K3: Y[:, n0:n0+128] = Z[:, l*64:+64] @ C[:, c0:c0+128]. K=64 resident.
// Grid (128, 16). 256 threads, warp tile 32x32, 3-pass split-bf16 HMMA.
// Dynamic smem 53248 B, cp.async loads.  (unchanged from passing R6 kernel)
// ---------------------------------------------------------------------------
__global__ __launch_bounds__(256) void gemm2(float* __restrict__ Y) {
    const int LDA = 72;   // Z: 64 x 72
    const int LDB = 136;  // C: 64 x 136
    const int Z_H = 0, Z_L = 4608, C_H = 9216, C_L = 17920;
    extern __shared__ __align__(16) __nv_bfloat16 sm2[];

    const int tid = threadIdx.x, lane = tid & 31, wid = tid >> 5;
    const int m0 = blockIdx.x * 64;
    const int n0 = blockIdx.y * 128;
    const int l = n0 >> 10;
    const int c0 = n0 & 1023;
    const int wm = (wid & 1) * 32, wn = (wid >> 1) * 32;

#pragma unroll
    for (int i = 0; i < 2; i++) {
        int p = tid + i * 256;
        int row = p >> 3, kq = (p & 7) * 8;
        CP16(sptr(&sm2[Z_H + row * LDA + kq]), &g_Zhi[(m0 + row) * 128 + l * 64 + kq]);
        CP16(sptr(&sm2[Z_L + row * LDA + kq]), &g_Zlo[(m0 + row) * 128 + l * 64 + kq]);
    }
#pragma unroll
    for (int i = 0; i < 4; i++) {
        int p = tid + i * 256;
        int row = p >> 4, cc = (p & 15) * 8;
        CP16(sptr(&sm2[C_H + row * LDB + cc]), &g_Chi[row * 1024 + c0 + cc]);
        CP16(sptr(&sm2[C_L + row * LDB + cc]), &g_Clo[row * 1024 + c0 + cc]);
    }
    CP_COMMIT();
    CP_WAIT0();
    __syncthreads();

    float acc[2][4][4];
#pragma unroll
    for (int mt = 0; mt < 2; mt++)
#pragma unroll
        for (int nt = 0; nt < 4; nt++)
#pragma unroll
            for (int e = 0; e < 4; e++) acc[mt][nt][e] = 0.0f;

#pragma unroll
    for (int kk = 0; kk < 64; kk += 16) {
        uint32_t ah[2][4], al[2][4];
#pragma unroll
        for (int mt = 0; mt < 2; mt++) {
            int arow = wm + mt * 16 + (lane & 15);
            int acol = kk + ((lane >> 4) << 3);
            ldm_a(sptr(&sm2[Z_H + arow * LDA + acol]), ah[mt]);
            ldm_a(sptr(&sm2[Z_L + arow * LDA + acol]), al[mt]);
        }
        uint32_t bh[2][4], bl[2][4];
        int brow = kk + (lane & 7) + ((lane >> 3) & 1) * 8;
#pragma unroll
        for (int h = 0; h < 2; h++) {
            int bcol = wn + h * 16 + (lane >> 4) * 8;
            ldm_bt(sptr(&sm2[C_H + brow * LDB + bcol]), bh[h]);
            ldm_bt(sptr(&sm2[C_L + brow * LDB + bcol]), bl[h]);
        }
#pragma unroll
        for (int mt = 0; mt < 2; mt++)
#pragma unroll
            for (int nt = 0; nt < 4; nt++) {
                int h = nt >> 1, q = (nt & 1) * 2;
                mma_bf16(acc[mt][nt], ah[mt], bh[h][q], bh[h][q + 1]);
                mma_bf16(acc[mt][nt], ah[mt], bl[h][q], bl[h][q + 1]);
                mma_bf16(acc[mt][nt], al[mt], bh[h][q], bh[h][q + 1]);
            }
    }

#pragma unroll
    for (int mt = 0; mt < 2; mt++)
#pragma unroll
        for (int nt = 0; nt < 4; nt++) {
            int row = m0 + wm + mt * 16 + (lane >> 2);
            int col = n0 + wn + nt * 8 + (lane & 3) * 2;
            const float* c = acc[mt][nt];
            *(float2*)&Y[row * 2048 + col] = make_float2(c[0], c[1]);
            *(float2*)&Y[(row + 8) * 2048 + col] = make_float2(c[2], c[3]);
        }
}

// ---------------------------------------------------------------------------
extern "C" void kernel_launch(void* const* d_in, const int* in_sizes, int n_in,
                              void* d_out, int out_size) {
    cudaFuncSetAttribute(gemm2, cudaFuncAttributeMaxDynamicSharedMemorySize, 53248);

    const float* x = (const float*)d_in[0];
    const float* f0 = (const float*)d_in[1];
    const float* f1 = (const float*)d_in[2];
    const float* f2 = (const float*)d_in[3];
    const float* f3 = (const float*)d_in[4];
    float* y = (float*)d_out;

    build_BC<<<1280, 256>>>(f0, f1, f2, f3);
    gemm1<<<128, 256>>>(x);
    dim3 g2(128, 16);
    gemm2<<<g2, 256, 53248>>>(y);
}

// round 12
// speedup vs baseline: 3.9834x; 1.2171x over previous
#include <cuda_runtime.h>
#include <cuda_bf16.h>
#include <cuda_fp16.h>
#include <cstdint>

// Y(8192x2048) = X(8192x2048) @ W(2048x2048), W = TR(f0,f1,f2,f3), rank-64 per i2-parity.
//   B[r][l*64+ab] = sum_k f0[a,i1,k] f1[k,i2,b],  i1=r>>5, i2=2(r&31)+l, ab=a*8+b
//   C[ab][i3*16+i4] = sum_k f2[b,i3,k] f3[k,i4,a]
//   Z = X @ B (8192x128);  Y[:, l*1024+c'] = Z[:, l*64:+64] @ C
// Both GEMMs: single-pass fp16 HMMA, fp32 accumulate (total err ~4.5e-4).

__device__ __half g_Bf16[2048 * 128];
__device__ __half g_Cf16[64 * 1024];
__device__ __half g_Zf16[8192 * 128];

static __device__ __forceinline__ uint32_t sptr(const void* p) {
    return (uint32_t)__cvta_generic_to_shared(p);
}
static __device__ __forceinline__ void ldm_a(uint32_t addr, uint32_t* r) {
    asm volatile("ldmatrix.sync.aligned.m8n8.x4.shared.b16 {%0,%1,%2,%3}, [%4];"
                 : "=r"(r[0]), "=r"(r[1]), "=r"(r[2]), "=r"(r[3]) : "r"(addr));
}
static __device__ __forceinline__ void ldm_bt(uint32_t addr, uint32_t* r) {
    asm volatile("ldmatrix.sync.aligned.m8n8.x4.trans.shared.b16 {%0,%1,%2,%3}, [%4];"
                 : "=r"(r[0]), "=r"(r[1]), "=r"(r[2]), "=r"(r[3]) : "r"(addr));
}
static __device__ __forceinline__ void mma_f16(float* c, const uint32_t* a,
                                               uint32_t b0, uint32_t b1) {
    asm volatile("mma.sync.aligned.m16n8k16.row.col.f32.f16.f16.f32 "
                 "{%0,%1,%2,%3}, {%4,%5,%6,%7}, {%8,%9}, {%0,%1,%2,%3};"
                 : "+f"(c[0]), "+f"(c[1]), "+f"(c[2]), "+f"(c[3])
                 : "r"(a[0]), "r"(a[1]), "r"(a[2]), "r"(a[3]), "r"(b0), "r"(b1));
}
#define CP16(dst, src)                                                        \
    asm volatile("cp.async.cg.shared.global [%0], [%1], 16;" ::"r"(dst), "l"(src))
#define CP_COMMIT() asm volatile("cp.async.commit_group;")
#define CP_WAIT0() asm volatile("cp.async.wait_group 0;")

static __device__ __forceinline__ uint2 f4_to_h4(float4 v) {
    __half2 p0 = __floats2half2_rn(v.x, v.y);
    __half2 p1 = __floats2half2_rn(v.z, v.w);
    return make_uint2(*reinterpret_cast<uint32_t*>(&p0),
                      *reinterpret_cast<uint32_t*>(&p1));
}

// ---------------------------------------------------------------------------
// K1: build B (fp16) and C (fp16) from TR factors.
// ---------------------------------------------------------------------------
__global__ void build_BC(const float* __restrict__ f0, const float* __restrict__ f1,
                         const float* __restrict__ f2, const float* __restrict__ f3) {
    int idx = blockIdx.x * blockDim.x + threadIdx.x;
    const int NB = 2048 * 128;
    if (idx < NB) {
        int r = idx >> 7, j = idx & 127;
        int l = j >> 6, ab = j & 63, a = ab >> 3, b = ab & 7;
        int i1 = r >> 5, i2 = ((r & 31) << 1) | l;
        float s = 0.0f;
#pragma unroll
        for (int k = 0; k < 8; k++)
            s = fmaf(f0[a * 512 + i1 * 8 + k], f1[k * 512 + i2 * 8 + b], s);
        g_Bf16[idx] = __float2half_rn(s);
    } else {
        int t = idx - NB;
        if (t < 64 * 1024) {
            int ab = t >> 10, c = t & 1023;
            int a = ab >> 3, b = ab & 7, i3 = c >> 4, i4 = c & 15;
            float s = 0.0f;
#pragma unroll
            for (int k = 0; k < 8; k++)
                s = fmaf(f2[b * 512 + i3 * 8 + k], f3[k * 128 + i4 * 8 + a], s);
            g_Cf16[t] = __float2half_rn(s);
        }
    }
}

// ---------------------------------------------------------------------------
// K2: Z = X @ B. M=8192 (32-row tiles -> grid 256, ~1.7 CTA/SM), N=128, K=2048.
// 256 threads, 8 warps (2Mx4N), warp tile 16x32. Double-buffered static smem.
// Single-pass fp16.
// ---------------------------------------------------------------------------
__global__ __launch_bounds__(256) void gemm1(const float* __restrict__ X) {
    const int LDA = 40;   // 32 x 40 fp16 per stage
    const int LDB = 136;  // 32 x 136 fp16 per stage
    __shared__ __align__(16) __half Ah[2][32 * 40];
    __shared__ __align__(16) __half Bh[2][32 * 136];

    const int tid = threadIdx.x, lane = tid & 31, wid = tid >> 5;
    const int m0 = blockIdx.x * 32;
    const int wm = (wid & 1) * 16, wn = (wid >> 1) * 32;

    const int xr = tid >> 3, xq = tid & 7;         // X row xr (0..31); float4 col xq
    const int br = tid >> 4, bc = (tid & 15) * 8;  // B rows br, br+16; col chunk bc

    float4 xf;

    float acc[4][4];
#pragma unroll
    for (int nt = 0; nt < 4; nt++)
#pragma unroll
        for (int e = 0; e < 4; e++) acc[nt][e] = 0.0f;

    // ---- prologue: stage 0 ----
    {
        CP16(sptr(&Bh[0][br * LDB + bc]), &g_Bf16[br * 128 + bc]);
        CP16(sptr(&Bh[0][(br + 16) * LDB + bc]), &g_Bf16[(br + 16) * 128 + bc]);
        CP_COMMIT();
        xf = *(const float4*)&X[(m0 + xr) * 2048 + xq * 4];
        *(uint2*)&Ah[0][xr * LDA + xq * 4] = f4_to_h4(xf);
    }

    for (int it = 0; it < 64; ++it) {
        CP_WAIT0();
        __syncthreads();
        const int cur = it & 1, nxt = (it + 1) & 1;
        const bool more = (it + 1 < 64);

        if (more) {
            int k0 = (it + 1) * 32;
            CP16(sptr(&Bh[nxt][br * LDB + bc]), &g_Bf16[(k0 + br) * 128 + bc]);
            CP16(sptr(&Bh[nxt][(br + 16) * LDB + bc]), &g_Bf16[(k0 + br + 16) * 128 + bc]);
            CP_COMMIT();
            xf = *(const float4*)&X[(m0 + xr) * 2048 + k0 + xq * 4];
        }

        // ---- compute current stage ----
#pragma unroll
        for (int kk = 0; kk < 32; kk += 16) {
            uint32_t ah[4];
            {
                int arow = wm + (lane & 15);
                int acol = kk + ((lane >> 4) << 3);
                ldm_a(sptr(&Ah[cur][arow * LDA + acol]), ah);
            }
            uint32_t bhr[2][4];
            int brow = kk + (lane & 7) + ((lane >> 3) & 1) * 8;
#pragma unroll
            for (int h = 0; h < 2; h++) {
                int bcol = wn + h * 16 + (lane >> 4) * 8;
                ldm_bt(sptr(&Bh[cur][brow * LDB + bcol]), bhr[h]);
            }
#pragma unroll
            for (int nt = 0; nt < 4; nt++) {
                int h = nt >> 1, q = (nt & 1) * 2;
                mma_f16(acc[nt], ah, bhr[h][q], bhr[h][q + 1]);
            }
        }

        if (more) *(uint2*)&Ah[nxt][xr * LDA + xq * 4] = f4_to_h4(xf);
    }

    // Epilogue: Z -> fp16 (cols 2j,2j+1 contiguous as __half2).
#pragma unroll
    for (int nt = 0; nt < 4; nt++) {
        int row = m0 + wm + (lane >> 2);
        int col = wn + nt * 8 + (lane & 3) * 2;
        const float* c = acc[nt];
#pragma unroll
        for (int half = 0; half < 2; half++) {
            int r = row + half * 8;
            __half2 z2 = __floats2half2_rn(c[half * 2 + 0], c[half * 2 + 1]);
            *(__half2*)&g_Zf16[r * 128 + col] = z2;
        }
    }
}

// ---------------------------------------------------------------------------
// K3: Y[:, n0:n0+128] = Z[:, l*64:+64] @ C[:, c0:c0+128]. K=64 resident.
// Block tile 128x128, grid (64, 16). 256 threads, 8 warps (2Mx4N),
// warp tile 64x32. Single-pass fp16. Static smem 35.8 KB.
// ---------------------------------------------------------------------------
__global__ __launch_bounds__(256) void gemm2(float* __restrict__ Y) {
    const int LDA = 72;   // Z: 128 x 72
    const int LDB = 136;  // C: 64 x 136
    __shared__ __align__(16) __half Zs[128 * 72];
    __shared__ __align__(16) __half Cs[64 * 136];

    const int tid = threadIdx.x, lane = tid & 31, wid = tid >> 5;
    const int m0 = blockIdx.x * 128;
    const int n0 = blockIdx.y * 128;
    const int l = n0 >> 10;
    const int c0 = n0 & 1023;
    const int wm = (wid & 1) * 64, wn = (wid >> 1) * 32;

    // Z tile 128x64 fp16: 1024 16B-chunks, 4/thread.
#pragma unroll
    for (int i = 0; i < 4; i++) {
        int p = tid + i * 256;
        int row = p >> 3, c8 = (p & 7) * 8;
        CP16(sptr(&Zs[row * LDA + c8]), &g_Zf16[(m0 + row) * 128 + l * 64 + c8]);
    }
    // C tile 64x128 fp16: 1024 16B-chunks, 4/thread.
#pragma unroll
    for (int i = 0; i < 4; i++) {
        int p = tid + i * 256;
        int row = p >> 4, c8 = (p & 15) * 8;
        CP16(sptr(&Cs[row * LDB + c8]), &g_Cf16[row * 1024 + c0 + c8]);
    }
    CP_COMMIT();
    CP_WAIT0();
    __syncthreads();

    float acc[4][4][4];
#pragma unroll
    for (int mt = 0; mt < 4; mt++)
#pragma unroll
        for (int nt = 0; nt < 4; nt++)
#pragma unroll
            for (int e = 0; e < 4; e++) acc[mt][nt][e] = 0.0f;

#pragma unroll
    for (int kk = 0; kk < 64; kk += 16) {
        uint32_t ah[4][4];
#pragma unroll
        for (int mt = 0; mt < 4; mt++) {
            int arow = wm + mt * 16 + (lane & 15);
            int acol = kk + ((lane >> 4) << 3);
            ldm_a(sptr(&Zs[arow * LDA + acol]), ah[mt]);
        }
        uint32_t bh[2][4];
        int brow = kk + (lane & 7) + ((lane >> 3) & 1) * 8;
#pragma unroll
        for (int h = 0; h < 2; h++) {
            int bcol = wn + h * 16 + (lane >> 4) * 8;
            ldm_bt(sptr(&Cs[brow * LDB + bcol]), bh[h]);
        }
#pragma unroll
        for (int mt = 0; mt < 4; mt++)
#pragma unroll
            for (int nt = 0; nt < 4; nt++) {
                int h = nt >> 1, q = (nt & 1) * 2;
                mma_f16(acc[mt][nt], ah[mt], bh[h][q], bh[h][q + 1]);
            }
    }

#pragma unroll
    for (int mt = 0; mt < 4; mt++)
#pragma unroll
        for (int nt = 0; nt < 4; nt++) {
            int row = m0 + wm + mt * 16 + (lane >> 2);
            int col = n0 + wn + nt * 8 + (lane & 3) * 2;
            const float* c = acc[mt][nt];
            *(float2*)&Y[row * 2048 + col] = make_float2(c[0], c[1]);
            *(float2*)&Y[(row + 8) * 2048 + col] = make_float2(c[2], c[3]);
        }
}

// ---------------------------------------------------------------------------
extern "C" void kernel_launch(void* const* d_in, const int* in_sizes, int n_in,
                              void* d_out, int out_size) {
    const float* x = (const float*)d_in[0];
    const float* f0 = (const float*)d_in[1];
    const float* f1 = (const float*)d_in[2];
    const float* f2 = (const float*)d_in[3];
    const float* f3 = (const float*)d_in[4];
    float* y = (float*)d_out;

    build_BC<<<1280, 256>>>(f0, f1, f2, f3);
    gemm1<<<256, 256>>>(x);
    dim3 g2(64, 16);
    gemm2<<<g2, 256>>>(y);
}

// round 13
// speedup vs baseline: 4.9116x; 1.2330x over previous
#include <cuda_runtime.h>
#include <cuda_bf16.h>
#include <cuda_fp16.h>
#include <cstdint>

// Y(8192x2048) = X(8192x2048) @ W(2048x2048), W = TR(f0,f1,f2,f3), rank-64 per i2-parity.
//   B[r][l*64+ab] = sum_k f0[a,i1,k] f1[k,i2,b],  i1=r>>5, i2=2(r&31)+l, ab=a*8+b
//   C[ab][i3*16+i4] = sum_k f2[b,i3,k] f3[k,i4,a]
//   Z = X @ B (8192x128);  Y[:, l*1024+c'] = Z[:, l*64:+64] @ C
// Both GEMMs: single-pass fp16 HMMA, fp32 accumulate (total err ~4.5e-4).
// gemm1 v2: X staged as fp32 via cp.async; A-fragments built by LDS+cvt
// (no LDG latency, no fp16-A round trip). BK=64, 32 iterations.

__device__ __half g_Bf16[2048 * 128];
__device__ __half g_Cf16[64 * 1024];
__device__ __half g_Zf16[8192 * 128];

static __device__ __forceinline__ uint32_t sptr(const void* p) {
    return (uint32_t)__cvta_generic_to_shared(p);
}
static __device__ __forceinline__ void ldm_a(uint32_t addr, uint32_t* r) {
    asm volatile("ldmatrix.sync.aligned.m8n8.x4.shared.b16 {%0,%1,%2,%3}, [%4];"
                 : "=r"(r[0]), "=r"(r[1]), "=r"(r[2]), "=r"(r[3]) : "r"(addr));
}
static __device__ __forceinline__ void ldm_bt(uint32_t addr, uint32_t* r) {
    asm volatile("ldmatrix.sync.aligned.m8n8.x4.trans.shared.b16 {%0,%1,%2,%3}, [%4];"
                 : "=r"(r[0]), "=r"(r[1]), "=r"(r[2]), "=r"(r[3]) : "r"(addr));
}
static __device__ __forceinline__ void mma_f16(float* c, const uint32_t* a,
                                               uint32_t b0, uint32_t b1) {
    asm volatile("mma.sync.aligned.m16n8k16.row.col.f32.f16.f16.f32 "
                 "{%0,%1,%2,%3}, {%4,%5,%6,%7}, {%8,%9}, {%0,%1,%2,%3};"
                 : "+f"(c[0]), "+f"(c[1]), "+f"(c[2]), "+f"(c[3])
                 : "r"(a[0]), "r"(a[1]), "r"(a[2]), "r"(a[3]), "r"(b0), "r"(b1));
}
#define CP16(dst, src)                                                        \
    asm volatile("cp.async.cg.shared.global [%0], [%1], 16;" ::"r"(dst), "l"(src))
#define CP_COMMIT() asm volatile("cp.async.commit_group;")
#define CP_WAIT0() asm volatile("cp.async.wait_group 0;")

static __device__ __forceinline__ uint32_t h2u(__half2 h) {
    return *reinterpret_cast<uint32_t*>(&h);
}

// ---------------------------------------------------------------------------
// K1: build B (fp16) and C (fp16) from TR factors.
// ---------------------------------------------------------------------------
__global__ void build_BC(const float* __restrict__ f0, const float* __restrict__ f1,
                         const float* __restrict__ f2, const float* __restrict__ f3) {
    int idx = blockIdx.x * blockDim.x + threadIdx.x;
    const int NB = 2048 * 128;
    if (idx < NB) {
        int r = idx >> 7, j = idx & 127;
        int l = j >> 6, ab = j & 63, a = ab >> 3, b = ab & 7;
        int i1 = r >> 5, i2 = ((r & 31) << 1) | l;
        float s = 0.0f;
#pragma unroll
        for (int k = 0; k < 8; k++)
            s = fmaf(f0[a * 512 + i1 * 8 + k], f1[k * 512 + i2 * 8 + b], s);
        g_Bf16[idx] = __float2half_rn(s);
    } else {
        int t = idx - NB;
        if (t < 64 * 1024) {
            int ab = t >> 10, c = t & 1023;
            int a = ab >> 3, b = ab & 7, i3 = c >> 4, i4 = c & 15;
            float s = 0.0f;
#pragma unroll
            for (int k = 0; k < 8; k++)
                s = fmaf(f2[b * 512 + i3 * 8 + k], f3[k * 128 + i4 * 8 + a], s);
            g_Cf16[t] = __float2half_rn(s);
        }
    }
}

// ---------------------------------------------------------------------------
// K2: Z = X @ B. M=8192 (32-row tiles, grid 256), N=128, K=2048, BK=64.
// 256 threads, 8 warps (2Mx4N), warp tile 16x32. Double-buffered dynamic smem:
//   per stage: Xs fp32 32x68 (8704 B) + Bs fp16 64x136 (17408 B) = 26112 B.
// All loads cp.async; A-fragments via LDS.64 + cvt (m16n8k16 layout).
// ---------------------------------------------------------------------------
__global__ __launch_bounds__(256) void gemm1(const float* __restrict__ X) {
    const int STAGE_B = 26112;   // bytes per stage
    const int XB = 8704;         // X region bytes (B region at +XB)
    const int LDX = 68;          // floats per X row (272 B, 16B-aligned)
    const int LDB = 136;         // halfs per B row (272 B)
    extern __shared__ __align__(16) char sm[];
    const uint32_t smb = sptr(sm);

    const int tid = threadIdx.x, lane = tid & 31, wid = tid >> 5;
    const int m0 = blockIdx.x * 32;
    const int wm = (wid & 1) * 16, wn = (wid >> 1) * 32;
    const int gid = lane >> 2, tig2 = (lane & 3) * 2;

    float acc[4][4];
#pragma unroll
    for (int nt = 0; nt < 4; nt++)
#pragma unroll
        for (int e = 0; e < 4; e++) acc[nt][e] = 0.0f;

    auto load_tile = [&](int it, int s) {
        const int k0 = it * 64;
        const uint32_t base = smb + s * STAGE_B;
        // X: 32 rows x 64 fp32 = 512 16B-chunks, 2/thread
#pragma unroll
        for (int i = 0; i < 2; i++) {
            int p = tid + i * 256;
            int row = p >> 4, c4 = (p & 15) * 4;
            CP16(base + row * 272 + c4 * 4, &X[(m0 + row) * 2048 + k0 + c4]);
        }
        // B: 64 rows x 128 fp16 = 1024 16B-chunks, 4/thread
#pragma unroll
        for (int i = 0; i < 4; i++) {
            int p = tid + i * 256;
            int row = p >> 4, c8 = (p & 15) * 8;
            CP16(base + XB + row * 272 + c8 * 2, &g_Bf16[(k0 + row) * 128 + c8]);
        }
        CP_COMMIT();
    };

    load_tile(0, 0);

    for (int it = 0; it < 32; ++it) {
        CP_WAIT0();
        __syncthreads();
        const int cur = it & 1;
        if (it + 1 < 32) load_tile(it + 1, (it + 1) & 1);

        const float* xs = (const float*)(sm + cur * STAGE_B);
        const uint32_t bsm = smb + cur * STAGE_B + XB;
        const int r0 = (wm + gid) * LDX, r1 = r0 + 8 * LDX;

#pragma unroll
        for (int kk = 0; kk < 64; kk += 16) {
            // A fragment (16x16) from fp32 smem: 4 x LDS.64 + cvt
            float2 v00 = *(const float2*)&xs[r0 + kk + tig2];
            float2 v10 = *(const float2*)&xs[r1 + kk + tig2];
            float2 v01 = *(const float2*)&xs[r0 + kk + 8 + tig2];
            float2 v11 = *(const float2*)&xs[r1 + kk + 8 + tig2];
            uint32_t a[4];
            a[0] = h2u(__floats2half2_rn(v00.x, v00.y));
            a[1] = h2u(__floats2half2_rn(v10.x, v10.y));
            a[2] = h2u(__floats2half2_rn(v01.x, v01.y));
            a[3] = h2u(__floats2half2_rn(v11.x, v11.y));
            // B fragments
            uint32_t bh[2][4];
            int brow = kk + (lane & 7) + ((lane >> 3) & 1) * 8;
#pragma unroll
            for (int h = 0; h < 2; h++) {
                int bcol = wn + h * 16 + (lane >> 4) * 8;
                ldm_bt(bsm + brow * 272 + bcol * 2, bh[h]);
            }
#pragma unroll
            for (int nt = 0; nt < 4; nt++) {
                int h = nt >> 1, q = (nt & 1) * 2;
                mma_f16(acc[nt], a, bh[h][q], bh[h][q + 1]);
            }
        }
    }

    // Epilogue: Z -> fp16 (cols 2j,2j+1 contiguous as __half2).
#pragma unroll
    for (int nt = 0; nt < 4; nt++) {
        int row = m0 + wm + (lane >> 2);
        int col = wn + nt * 8 + (lane & 3) * 2;
        const float* c = acc[nt];
#pragma unroll
        for (int half = 0; half < 2; half++) {
            int r = row + half * 8;
            __half2 z2 = __floats2half2_rn(c[half * 2 + 0], c[half * 2 + 1]);
            *(__half2*)&g_Zf16[r * 128 + col] = z2;
        }
    }
}

// ---------------------------------------------------------------------------
// K3: Y[:, n0:n0+128] = Z[:, l*64:+64] @ C[:, c0:c0+128]. K=64 resident.
// Block tile 128x128, grid (64, 16). 256 threads, 8 warps (2Mx4N),
// warp tile 64x32. Single-pass fp16. Static smem 35.8 KB.  (unchanged R12)
// ---------------------------------------------------------------------------
__global__ __launch_bounds__(256) void gemm2(float* __restrict__ Y) {
    const int LDA = 72;   // Z: 128 x 72
    const int LDB = 136;  // C: 64 x 136
    __shared__ __align__(16) __half Zs[128 * 72];
    __shared__ __align__(16) __half Cs[64 * 136];

    const int tid = threadIdx.x, lane = tid & 31, wid = tid >> 5;
    const int m0 = blockIdx.x * 128;
    const int n0 = blockIdx.y * 128;
    const int l = n0 >> 10;
    const int c0 = n0 & 1023;
    const int wm = (wid & 1) * 64, wn = (wid >> 1) * 32;

#pragma unroll
    for (int i = 0; i < 4; i++) {
        int p = tid + i * 256;
        int row = p >> 3, c8 = (p & 7) * 8;
        CP16(sptr(&Zs[row * LDA + c8]), &g_Zf16[(m0 + row) * 128 + l * 64 + c8]);
    }
#pragma unroll
    for (int i = 0; i < 4; i++) {
        int p = tid + i * 256;
        int row = p >> 4, c8 = (p & 15) * 8;
        CP16(sptr(&Cs[row * LDB + c8]), &g_Cf16[row * 1024 + c0 + c8]);
    }
    CP_COMMIT();
    CP_WAIT0();
    __syncthreads();

    float acc[4][4][4];
#pragma unroll
    for (int mt = 0; mt < 4; mt++)
#pragma unroll
        for (int nt = 0; nt < 4; nt++)
#pragma unroll
            for (int e = 0; e < 4; e++) acc[mt][nt][e] = 0.0f;

#pragma unroll
    for (int kk = 0; kk < 64; kk += 16) {
        uint32_t ah[4][4];
#pragma unroll
        for (int mt = 0; mt < 4; mt++) {
            int arow = wm + mt * 16 + (lane & 15);
            int acol = kk + ((lane >> 4) << 3);
            ldm_a(sptr(&Zs[arow * LDA + acol]), ah[mt]);
        }
        uint32_t bh[2][4];
        int brow = kk + (lane & 7) + ((lane >> 3) & 1) * 8;
#pragma unroll
        for (int h = 0; h < 2; h++) {
            int bcol = wn + h * 16 + (lane >> 4) * 8;
            ldm_bt(sptr(&Cs[brow * LDB + bcol]), bh[h]);
        }
#pragma unroll
        for (int mt = 0; mt < 4; mt++)
#pragma unroll
            for (int nt = 0; nt < 4; nt++) {
                int h = nt >> 1, q = (nt & 1) * 2;
                mma_f16(acc[mt][nt], ah[mt], bh[h][q], bh[h][q + 1]);
            }
    }

#pragma unroll
    for (int mt = 0; mt < 4; mt++)
#pragma unroll
        for (int nt = 0; nt < 4; nt++) {
            int row = m0 + wm + mt * 16 + (lane >> 2);
            int col = n0 + wn + nt * 8 + (lane & 3) * 2;
            const float* c = acc[mt][nt];
            *(float2*)&Y[row * 2048 + col] = make_float2(c[0], c[1]);
            *(float2*)&Y[(row + 8) * 2048 + col] = make_float2(c[2], c[3]);
        }
}

// ---------------------------------------------------------------------------
extern "C" void kernel_launch(void* const* d_in, const int* in_sizes, int n_in,
                              void* d_out, int out_size) {
    cudaFuncSetAttribute(gemm1, cudaFuncAttributeMaxDynamicSharedMemorySize, 52224);

    const float* x = (const float*)d_in[0];
    const float* f0 = (const float*)d_in[1];
    const float* f1 = (const float*)d_in[2];
    const float* f2 = (const float*)d_in[3];
    const float* f3 = (const float*)d_in[4];
    float* y = (float*)d_out;

    build_BC<<<1280, 256>>>(f0, f1, f2, f3);
    gemm1<<<256, 256, 52224>>>(x);
    dim3 g2(64, 16);
    gemm2<<<g2, 256>>>(y);
}